// round 2
// baseline (speedup 1.0000x reference)
#include <cuda_runtime.h>
#include <math.h>

#define SEQ   4096
#define DM    768
#define NH    12
#define DH    64
#define QKVC  2304          // 3 * DM
#define SCALE 0.125f        // 1/sqrt(64)

// Scratch (allocations forbidden; __device__ globals are the sanctioned path)
__device__ float g_qkv[SEQ * QKVC];   // [S, 3*DM]  (Q | K | V per row)
__device__ float g_attn[SEQ * DM];    // attention output, heads concatenated

// ---------------------------------------------------------------------------
// C[M,N] = A[M,K] @ B[N,K]^T + bias[N]
// BM=BN=128, BK=16, 256 threads, 8x8 register micro-tile.
// smem floats per FMA = 16/64 = 0.25 (was 0.375) -> FMA-pipe bound.
// ---------------------------------------------------------------------------
__global__ __launch_bounds__(256, 2) void gemm_nt_bias(
    const float* __restrict__ A, const float* __restrict__ B,
    const float* __restrict__ bias, float* __restrict__ C,
    int M, int N, int K)
{
    __shared__ float As[16][132];   // [k][m], pad 132 (mod 32 = 4) to soften STS conflicts
    __shared__ float Bs[16][132];   // [k][n]

    const int tid = threadIdx.x;
    const int tx  = tid & 15;      // 0..15 -> N direction (8 cols each)
    const int ty  = tid >> 4;      // 0..15 -> M direction (8 rows each)
    const int m0  = blockIdx.y * 128;
    const int n0  = blockIdx.x * 128;

    float acc[8][8];
#pragma unroll
    for (int i = 0; i < 8; i++)
#pragma unroll
        for (int j = 0; j < 8; j++) acc[i][j] = 0.f;

    for (int kt = 0; kt < K; kt += 16) {
#pragma unroll
        for (int q = 0; q < 2; q++) {
            int idx = q * 256 + tid;          // 0..511 float4 slots
            int row = idx >> 2;               // 0..127
            int c   = (idx & 3) << 2;         // 0,4,8,12
            float4 va = *(const float4*)(A + (size_t)(m0 + row) * K + kt + c);
            As[c + 0][row] = va.x; As[c + 1][row] = va.y;
            As[c + 2][row] = va.z; As[c + 3][row] = va.w;
            float4 vb = *(const float4*)(B + (size_t)(n0 + row) * K + kt + c);
            Bs[c + 0][row] = vb.x; Bs[c + 1][row] = vb.y;
            Bs[c + 2][row] = vb.z; Bs[c + 3][row] = vb.w;
        }
        __syncthreads();

#pragma unroll
        for (int kk = 0; kk < 16; kk++) {
            float4 a0 = *(const float4*)&As[kk][ty * 8];
            float4 a1 = *(const float4*)&As[kk][ty * 8 + 4];
            float4 b0 = *(const float4*)&Bs[kk][tx * 8];
            float4 b1 = *(const float4*)&Bs[kk][tx * 8 + 4];
            float a[8] = {a0.x, a0.y, a0.z, a0.w, a1.x, a1.y, a1.z, a1.w};
            float b[8] = {b0.x, b0.y, b0.z, b0.w, b1.x, b1.y, b1.z, b1.w};
#pragma unroll
            for (int i = 0; i < 8; i++)
#pragma unroll
                for (int j = 0; j < 8; j++)
                    acc[i][j] += a[i] * b[j];
        }
        __syncthreads();
    }

    const int c0 = n0 + tx * 8;
    float4 bv0 = *(const float4*)(bias + c0);
    float4 bv1 = *(const float4*)(bias + c0 + 4);
#pragma unroll
    for (int i = 0; i < 8; i++) {
        int r = m0 + ty * 8 + i;
        float4 o0, o1;
        o0.x = acc[i][0] + bv0.x; o0.y = acc[i][1] + bv0.y;
        o0.z = acc[i][2] + bv0.z; o0.w = acc[i][3] + bv0.w;
        o1.x = acc[i][4] + bv1.x; o1.y = acc[i][5] + bv1.y;
        o1.z = acc[i][6] + bv1.z; o1.w = acc[i][7] + bv1.w;
        *(float4*)(C + (size_t)r * N + c0)     = o0;
        *(float4*)(C + (size_t)r * N + c0 + 4) = o1;
    }
}

// ---------------------------------------------------------------------------
// Flash-style causal attention, 4 threads per query row.
// grid = (12 heads, 64 q-tiles), 256 threads. Thread = (row 0..63, part 0..3).
// Each thread owns 16 of the 64 head dims; score partials reduced with 2
// shfl_xor. Regs ~85 (occ up), longest block's serial work cut 4x.
// ---------------------------------------------------------------------------
__global__ __launch_bounds__(256) void attn_kernel()
{
    const int h    = blockIdx.x;
    const int qt   = (int)gridDim.y - 1 - (int)blockIdx.y;  // big tiles first
    const int tid  = threadIdx.x;
    const int row  = tid >> 2;        // 0..63
    const int part = tid & 3;         // 0..3 -> dims part*16 .. part*16+15
    const int qi   = qt * 64 + row;

    __shared__ float Ks[32][64];
    __shared__ float Vs[32][64];

    // Q slice (16 dims), pre-scaled
    const float* qp = g_qkv + (size_t)qi * QKVC + h * DH + part * 16;
    float4 q[4];
#pragma unroll
    for (int i = 0; i < 4; i++) {
        float4 v = *(const float4*)(qp + i * 4);
        q[i] = make_float4(v.x * SCALE, v.y * SCALE, v.z * SCALE, v.w * SCALE);
    }

    float4 o[4];
#pragma unroll
    for (int i = 0; i < 4; i++) o[i] = make_float4(0.f, 0.f, 0.f, 0.f);
    float m = -INFINITY, l = 0.f;

    const int kmax = (qt + 1) * 64;
    for (int k0 = 0; k0 < kmax; k0 += 32) {
        __syncthreads();
#pragma unroll
        for (int i = 0; i < 2; i++) {
            int idx = i * 256 + tid;          // 0..511 float4 slots
            int r   = idx >> 4;               // 0..31
            int c   = (idx & 15) << 2;        // 0..60
            const float* base = g_qkv + (size_t)(k0 + r) * QKVC + DM + h * DH + c;
            *(float4*)&Ks[r][c] = *(const float4*)base;
            *(float4*)&Vs[r][c] = *(const float4*)(base + DM);
        }
        __syncthreads();

        // partial scores over 16 dims, then butterfly-reduce across 4 parts
        float s[32];
#pragma unroll
        for (int k = 0; k < 32; k++) {
            const float* kp = &Ks[k][part * 16];
            float4 k0v = *(const float4*)(kp + 0);
            float4 k1v = *(const float4*)(kp + 4);
            float4 k2v = *(const float4*)(kp + 8);
            float4 k3v = *(const float4*)(kp + 12);
            float a0 = q[0].x * k0v.x + q[0].y * k0v.y + q[0].z * k0v.z + q[0].w * k0v.w;
            float a1 = q[1].x * k1v.x + q[1].y * k1v.y + q[1].z * k1v.z + q[1].w * k1v.w;
            a0 += q[2].x * k2v.x + q[2].y * k2v.y + q[2].z * k2v.z + q[2].w * k2v.w;
            a1 += q[3].x * k3v.x + q[3].y * k3v.y + q[3].z * k3v.z + q[3].w * k3v.w;
            float acc = a0 + a1;
            acc += __shfl_xor_sync(0xffffffffu, acc, 1);
            acc += __shfl_xor_sync(0xffffffffu, acc, 2);
            s[k] = (k0 + k <= qi) ? acc : -INFINITY;
        }

        // online softmax (identical across the 4 parts of a row)
        float tm = s[0];
#pragma unroll
        for (int k = 1; k < 32; k++) tm = fmaxf(tm, s[k]);
        float mn    = fmaxf(m, tm);
        float alpha = __expf(m - mn);         // m=-inf first iter -> 0
        float psum  = 0.f;
#pragma unroll
        for (int k = 0; k < 32; k++) {
            s[k] = __expf(s[k] - mn);         // -inf -> 0
            psum += s[k];
        }
        l = l * alpha + psum;
        m = mn;

        // O(part's 16 dims) = O*alpha + P @ V
#pragma unroll
        for (int d = 0; d < 4; d++) {
            float4 ov = o[d];
            ov.x *= alpha; ov.y *= alpha; ov.z *= alpha; ov.w *= alpha;
#pragma unroll
            for (int k = 0; k < 32; k++) {
                float4 v = *(const float4*)&Vs[k][part * 16 + d * 4];
                ov.x += s[k] * v.x;
                ov.y += s[k] * v.y;
                ov.z += s[k] * v.z;
                ov.w += s[k] * v.w;
            }
            o[d] = ov;
        }
    }

    const float inv = 1.f / l;
    float* op = g_attn + (size_t)qi * DM + h * DH + part * 16;
#pragma unroll
    for (int d = 0; d < 4; d++) {
        float4 r = make_float4(o[d].x * inv, o[d].y * inv, o[d].z * inv, o[d].w * inv);
        *(float4*)(op + d * 4) = r;
    }
}

// ---------------------------------------------------------------------------
extern "C" void kernel_launch(void* const* d_in, const int* in_sizes, int n_in,
                              void* d_out, int out_size)
{
    const float* x     = (const float*)d_in[0];
    const float* W_in  = (const float*)d_in[1];
    const float* b_in  = (const float*)d_in[2];
    const float* W_out = (const float*)d_in[3];
    const float* b_out = (const float*)d_in[4];
    float* out = (float*)d_out;

    float* qkv_p;  cudaGetSymbolAddress((void**)&qkv_p,  g_qkv);
    float* attn_p; cudaGetSymbolAddress((void**)&attn_p, g_attn);

    // 1) qkv = x @ W_in^T + b_in   -> g_qkv [4096, 2304]
    {
        dim3 grid(QKVC / 128, SEQ / 128);
        gemm_nt_bias<<<grid, 256>>>(x, W_in, b_in, qkv_p, SEQ, QKVC, DM);
    }
    // 2) causal multi-head attention -> g_attn [4096, 768]
    {
        dim3 grid(NH, SEQ / 64);
        attn_kernel<<<grid, 256>>>();
    }
    // 3) out = attn @ W_out^T + b_out -> d_out
    {
        dim3 grid(DM / 128, SEQ / 128);
        gemm_nt_bias<<<grid, 256>>>(attn_p, W_out, b_out, out, SEQ, DM, DM);
    }
}

// round 4
// speedup vs baseline: 5.4815x; 5.4815x over previous
#include <cuda_runtime.h>
#include <cuda_fp16.h>
#include <math.h>
#include <cstdint>

#define SEQ   4096
#define DM    768
#define NH    12
#define DH    64
#define QKVC  2304          // 3 * DM
#define SCALE 0.125f        // 1/sqrt(64)
#define NEG   -1.0e30f

// ------------------------- scratch (__device__ globals) --------------------
__device__ float  g_qkv[SEQ * QKVC];        // [S, 3*DM] fp32 (Q | K | V)
__device__ float  g_attn[SEQ * DM];         // attention out fp32
__device__ __half g_q16[NH * SEQ * DH];     // [h][s][d], pre-scaled by SCALE
__device__ __half g_k16[NH * SEQ * DH];     // [h][s][d]
__device__ __half g_v16[NH * SEQ * DH];     // [h][s][d]

// ---------------------------- PTX helpers ----------------------------------
__device__ __forceinline__ uint32_t smem_u32(const void* p) {
    uint32_t a;
    asm("{ .reg .u64 t; cvta.to.shared.u64 t, %1; cvt.u32.u64 %0, t; }" : "=r"(a) : "l"(p));
    return a;
}
__device__ __forceinline__ void ldmx4(uint32_t* r, uint32_t addr) {
    asm volatile("ldmatrix.sync.aligned.m8n8.x4.shared.b16 {%0,%1,%2,%3}, [%4];"
        : "=r"(r[0]), "=r"(r[1]), "=r"(r[2]), "=r"(r[3]) : "r"(addr));
}
__device__ __forceinline__ void ldmx4t(uint32_t* r, uint32_t addr) {
    asm volatile("ldmatrix.sync.aligned.m8n8.x4.trans.shared.b16 {%0,%1,%2,%3}, [%4];"
        : "=r"(r[0]), "=r"(r[1]), "=r"(r[2]), "=r"(r[3]) : "r"(addr));
}
__device__ __forceinline__ void mma16816(float* d, const uint32_t* a,
                                         const uint32_t* b, const float* c) {
    asm volatile(
        "mma.sync.aligned.m16n8k16.row.col.f32.f16.f16.f32 "
        "{%0,%1,%2,%3}, {%4,%5,%6,%7}, {%8,%9}, {%10,%11,%12,%13};"
        : "=f"(d[0]), "=f"(d[1]), "=f"(d[2]), "=f"(d[3])
        : "r"(a[0]), "r"(a[1]), "r"(a[2]), "r"(a[3]),
          "r"(b[0]), "r"(b[1]),
          "f"(c[0]), "f"(c[1]), "f"(c[2]), "f"(c[3]));
}
__device__ __forceinline__ uint32_t packh2(float x, float y) {
    __half2 h = __floats2half2_rn(x, y);
    return *(uint32_t*)&h;
}

// ---------------------------------------------------------------------------
// GEMM (FFMA): C[M,N] = A[M,K] @ B[N,K]^T + bias[N].  128x128x16, 256 thr.
// ---------------------------------------------------------------------------
__global__ __launch_bounds__(256, 2) void gemm_nt_bias(
    const float* __restrict__ A, const float* __restrict__ B,
    const float* __restrict__ bias, float* __restrict__ C,
    int M, int N, int K)
{
    __shared__ float As[16][132];
    __shared__ float Bs[16][132];

    const int tid = threadIdx.x;
    const int tx  = tid & 15;
    const int ty  = tid >> 4;
    const int m0  = blockIdx.y * 128;
    const int n0  = blockIdx.x * 128;

    float acc[8][8];
#pragma unroll
    for (int i = 0; i < 8; i++)
#pragma unroll
        for (int j = 0; j < 8; j++) acc[i][j] = 0.f;

    for (int kt = 0; kt < K; kt += 16) {
#pragma unroll
        for (int q = 0; q < 2; q++) {
            int idx = q * 256 + tid;
            int row = idx >> 2;
            int c   = (idx & 3) << 2;
            float4 va = *(const float4*)(A + (size_t)(m0 + row) * K + kt + c);
            As[c + 0][row] = va.x; As[c + 1][row] = va.y;
            As[c + 2][row] = va.z; As[c + 3][row] = va.w;
            float4 vb = *(const float4*)(B + (size_t)(n0 + row) * K + kt + c);
            Bs[c + 0][row] = vb.x; Bs[c + 1][row] = vb.y;
            Bs[c + 2][row] = vb.z; Bs[c + 3][row] = vb.w;
        }
        __syncthreads();
#pragma unroll
        for (int kk = 0; kk < 16; kk++) {
            float4 a0 = *(const float4*)&As[kk][ty * 8];
            float4 a1 = *(const float4*)&As[kk][ty * 8 + 4];
            float4 b0 = *(const float4*)&Bs[kk][tx * 8];
            float4 b1 = *(const float4*)&Bs[kk][tx * 8 + 4];
            float a[8] = {a0.x, a0.y, a0.z, a0.w, a1.x, a1.y, a1.z, a1.w};
            float b[8] = {b0.x, b0.y, b0.z, b0.w, b1.x, b1.y, b1.z, b1.w};
#pragma unroll
            for (int i = 0; i < 8; i++)
#pragma unroll
                for (int j = 0; j < 8; j++)
                    acc[i][j] += a[i] * b[j];
        }
        __syncthreads();
    }

    const int c0 = n0 + tx * 8;
    float4 bv0 = *(const float4*)(bias + c0);
    float4 bv1 = *(const float4*)(bias + c0 + 4);
#pragma unroll
    for (int i = 0; i < 8; i++) {
        int r = m0 + ty * 8 + i;
        float4 o0, o1;
        o0.x = acc[i][0] + bv0.x; o0.y = acc[i][1] + bv0.y;
        o0.z = acc[i][2] + bv0.z; o0.w = acc[i][3] + bv0.w;
        o1.x = acc[i][4] + bv1.x; o1.y = acc[i][5] + bv1.y;
        o1.z = acc[i][6] + bv1.z; o1.w = acc[i][7] + bv1.w;
        *(float4*)(C + (size_t)r * N + c0)     = o0;
        *(float4*)(C + (size_t)r * N + c0 + 4) = o1;
    }
}

// ---------------------------------------------------------------------------
// Convert g_qkv(fp32) -> fp16 Q (scaled), K, V in [h][s][d] layout.
// grid (NH, SEQ/256), 256 threads.
// ---------------------------------------------------------------------------
__global__ __launch_bounds__(256) void convert_kernel()
{
    const int h   = blockIdx.x;
    const int s0  = blockIdx.y * 256;
    const int tid = threadIdx.x;

#pragma unroll
    for (int i = 0; i < 16; i++) {
        int idx = i * 256 + tid;           // 0..4095
        int row = idx >> 4;                // 0..255
        int c4  = (idx & 15) * 4;          // 0..60
        const float* base = g_qkv + (size_t)(s0 + row) * QKVC + h * DH + c4;
        float4 q = *(const float4*)(base);
        float4 k = *(const float4*)(base + DM);
        float4 v = *(const float4*)(base + 2 * DM);

        size_t o = ((size_t)h * SEQ + s0 + row) * DH + c4;
        uint2 qu, ku, vu;
        qu.x = packh2(q.x * SCALE, q.y * SCALE);
        qu.y = packh2(q.z * SCALE, q.w * SCALE);
        ku.x = packh2(k.x, k.y);  ku.y = packh2(k.z, k.w);
        vu.x = packh2(v.x, v.y);  vu.y = packh2(v.z, v.w);
        *(uint2*)(g_q16 + o) = qu;
        *(uint2*)(g_k16 + o) = ku;
        *(uint2*)(g_v16 + o) = vu;
    }
}

// ---------------------------------------------------------------------------
// HMMA flash attention.  grid (NH, SEQ/128), 256 threads (8 warps).
// Warp w owns q rows qt*128 + w*16 .. +15.  64-key tiles.
// ---------------------------------------------------------------------------
#define KSTR 72   // smem row stride in halves (conflict-free ldmatrix)

__global__ __launch_bounds__(256) void attn_mma_kernel()
{
    __shared__ __half sm[128 * KSTR];    // Q staging (128x64) -> later K(64)+V(64)

    const int tid  = threadIdx.x;
    const int wid  = tid >> 5;
    const int lane = tid & 31;
    const int h    = blockIdx.x;
    const int qt   = (int)gridDim.y - 1 - (int)blockIdx.y;   // long blocks first
    const int q0   = qt * 128;
    const int wq   = q0 + wid * 16;      // warp's first q row

    const uint32_t smb = smem_u32(sm);

    // ---- stage Q tile, extract A-fragments (held in regs for whole kernel) --
    {
        const __half* qg = g_q16 + ((size_t)h * SEQ + q0) * DH;
#pragma unroll
        for (int i = 0; i < 4; i++) {
            int idx = i * 256 + tid;          // 1024 16B-chunks
            int row = idx >> 3;
            int g   = idx & 7;
            *(uint4*)(sm + row * KSTR + g * 8) = *((const uint4*)(qg + (size_t)row * DH) + g);
        }
    }
    __syncthreads();

    uint32_t qa[4][4];
    {
        int row  = wid * 16 + (lane & 15);
        int colh = (lane >> 4) * 8;
#pragma unroll
        for (int kb = 0; kb < 4; kb++)
            ldmx4(qa[kb], smb + (uint32_t)(row * KSTR + kb * 16 + colh) * 2);
    }
    __syncthreads();

    __half* smK = sm;                 // 64 x KSTR
    __half* smV = sm + 64 * KSTR;     // 64 x KSTR
    const uint32_t smKb = smb;
    const uint32_t smVb = smb + 64 * KSTR * 2;

    float O[8][4];
#pragma unroll
    for (int d = 0; d < 8; d++)
#pragma unroll
        for (int j = 0; j < 4; j++) O[d][j] = 0.f;
    float m0 = NEG, m1 = NEG, l0 = 0.f, l1 = 0.f;

    const int ktiles = (qt + 1) * 2;
    for (int t = 0; t < ktiles; t++) {
        const int k0 = t * 64;

        // ---- cooperative K/V tile load ----
        {
            const __half* kg = g_k16 + ((size_t)h * SEQ + k0) * DH;
            const __half* vg = g_v16 + ((size_t)h * SEQ + k0) * DH;
#pragma unroll
            for (int i = 0; i < 2; i++) {
                int idx = i * 256 + tid;      // 512 chunks
                int row = idx >> 3;
                int g   = idx & 7;
                *(uint4*)(smK + row * KSTR + g * 8) = *((const uint4*)(kg + (size_t)row * DH) + g);
                *(uint4*)(smV + row * KSTR + g * 8) = *((const uint4*)(vg + (size_t)row * DH) + g);
            }
        }
        __syncthreads();

        if (k0 <= wq + 15) {   // tile has at least one unmasked key for this warp
            // ---- S = Q @ K^T  (c[nb][4], nb = 8-key block) ----
            float c[8][4];
#pragma unroll
            for (int nb = 0; nb < 8; nb++)
#pragma unroll
                for (int j = 0; j < 4; j++) c[nb][j] = 0.f;

#pragma unroll
            for (int nb = 0; nb < 8; nb++) {
                uint32_t kk[8];
                uint32_t rowa = nb * 8 + (lane & 7);
                uint32_t cola = (lane >> 3) * 8;                 // 0,8,16,24
                ldmx4(kk,     smKb + (rowa * KSTR + cola) * 2);        // d 0..31 -> kb0,kb1
                ldmx4(kk + 4, smKb + (rowa * KSTR + 32 + cola) * 2);   // d 32..63 -> kb2,kb3
#pragma unroll
                for (int kb = 0; kb < 4; kb++)
                    mma16816(c[nb], qa[kb], kk + kb * 2, c[nb]);
            }

            // ---- causal mask (only needed near diagonal) ----
            if (k0 + 63 > wq) {
                int r0 = wq + (lane >> 2);
                int r1 = r0 + 8;
                int cb = k0 + (lane & 3) * 2;
#pragma unroll
                for (int nb = 0; nb < 8; nb++) {
                    int col = cb + nb * 8;
                    if (col     > r0) c[nb][0] = NEG;
                    if (col + 1 > r0) c[nb][1] = NEG;
                    if (col     > r1) c[nb][2] = NEG;
                    if (col + 1 > r1) c[nb][3] = NEG;
                }
            }

            // ---- online softmax (row stats across quad lanes) ----
            float tm0 = NEG, tm1 = NEG;
#pragma unroll
            for (int nb = 0; nb < 8; nb++) {
                tm0 = fmaxf(tm0, fmaxf(c[nb][0], c[nb][1]));
                tm1 = fmaxf(tm1, fmaxf(c[nb][2], c[nb][3]));
            }
            tm0 = fmaxf(tm0, __shfl_xor_sync(0xffffffffu, tm0, 1));
            tm0 = fmaxf(tm0, __shfl_xor_sync(0xffffffffu, tm0, 2));
            tm1 = fmaxf(tm1, __shfl_xor_sync(0xffffffffu, tm1, 1));
            tm1 = fmaxf(tm1, __shfl_xor_sync(0xffffffffu, tm1, 2));

            float mn0 = fmaxf(m0, tm0), mn1 = fmaxf(m1, tm1);
            float a0  = __expf(m0 - mn0), a1 = __expf(m1 - mn1);
            float ps0 = 0.f, ps1 = 0.f;
#pragma unroll
            for (int nb = 0; nb < 8; nb++) {
                c[nb][0] = __expf(c[nb][0] - mn0);
                c[nb][1] = __expf(c[nb][1] - mn0);
                c[nb][2] = __expf(c[nb][2] - mn1);
                c[nb][3] = __expf(c[nb][3] - mn1);
                ps0 += c[nb][0] + c[nb][1];
                ps1 += c[nb][2] + c[nb][3];
            }
            ps0 += __shfl_xor_sync(0xffffffffu, ps0, 1);
            ps0 += __shfl_xor_sync(0xffffffffu, ps0, 2);
            ps1 += __shfl_xor_sync(0xffffffffu, ps1, 1);
            ps1 += __shfl_xor_sync(0xffffffffu, ps1, 2);
            l0 = l0 * a0 + ps0;  m0 = mn0;
            l1 = l1 * a1 + ps1;  m1 = mn1;

#pragma unroll
            for (int d = 0; d < 8; d++) {
                O[d][0] *= a0; O[d][1] *= a0;
                O[d][2] *= a1; O[d][3] *= a1;
            }

            // ---- repack P (S c-frags -> A-frags, FA2 trick) ----
            uint32_t pa[4][4];
#pragma unroll
            for (int kb = 0; kb < 4; kb++) {
                pa[kb][0] = packh2(c[2 * kb][0],     c[2 * kb][1]);
                pa[kb][1] = packh2(c[2 * kb][2],     c[2 * kb][3]);
                pa[kb][2] = packh2(c[2 * kb + 1][0], c[2 * kb + 1][1]);
                pa[kb][3] = packh2(c[2 * kb + 1][2], c[2 * kb + 1][3]);
            }

            // ---- O += P @ V ----
#pragma unroll
            for (int db = 0; db < 8; db++) {
                uint32_t v0[4], v1[4];
                ldmx4t(v0, smVb + (uint32_t)((lane)      * KSTR + db * 8) * 2);  // keys 0..31
                ldmx4t(v1, smVb + (uint32_t)((32 + lane) * KSTR + db * 8) * 2);  // keys 32..63
                mma16816(O[db], pa[0], v0,     O[db]);
                mma16816(O[db], pa[1], v0 + 2, O[db]);
                mma16816(O[db], pa[2], v1,     O[db]);
                mma16816(O[db], pa[3], v1 + 2, O[db]);
            }
        }
        __syncthreads();
    }

    // ---- epilogue: divide by l, store fp32 ----
    const float inv0 = 1.f / l0, inv1 = 1.f / l1;
    const int r0 = wq + (lane >> 2);
    const int r1 = r0 + 8;
    float* o0 = g_attn + (size_t)r0 * DM + h * DH + (lane & 3) * 2;
    float* o1 = g_attn + (size_t)r1 * DM + h * DH + (lane & 3) * 2;
#pragma unroll
    for (int db = 0; db < 8; db++) {
        float2 w0 = make_float2(O[db][0] * inv0, O[db][1] * inv0);
        float2 w1 = make_float2(O[db][2] * inv1, O[db][3] * inv1);
        *(float2*)(o0 + db * 8) = w0;
        *(float2*)(o1 + db * 8) = w1;
    }
}

// ---------------------------------------------------------------------------
extern "C" void kernel_launch(void* const* d_in, const int* in_sizes, int n_in,
                              void* d_out, int out_size)
{
    const float* x     = (const float*)d_in[0];
    const float* W_in  = (const float*)d_in[1];
    const float* b_in  = (const float*)d_in[2];
    const float* W_out = (const float*)d_in[3];
    const float* b_out = (const float*)d_in[4];
    float* out = (float*)d_out;

    float* qkv_p;  cudaGetSymbolAddress((void**)&qkv_p,  g_qkv);
    float* attn_p; cudaGetSymbolAddress((void**)&attn_p, g_attn);

    // 1) qkv = x @ W_in^T + b_in
    {
        dim3 grid(QKVC / 128, SEQ / 128);
        gemm_nt_bias<<<grid, 256>>>(x, W_in, b_in, qkv_p, SEQ, QKVC, DM);
    }
    // 2) fp32 -> fp16 (+ Q scale), per-head layout
    {
        dim3 grid(NH, SEQ / 256);
        convert_kernel<<<grid, 256>>>();
    }
    // 3) HMMA causal flash attention
    {
        dim3 grid(NH, SEQ / 128);
        attn_mma_kernel<<<grid, 256>>>();
    }
    // 4) out = attn @ W_out^T + b_out
    {
        dim3 grid(DM / 128, SEQ / 128);
        gemm_nt_bias<<<grid, 256>>>(attn_p, W_out, b_out, out, SEQ, DM, DM);
    }
}

// round 5
// speedup vs baseline: 15.1912x; 2.7714x over previous
#include <cuda_runtime.h>
#include <cuda_fp16.h>
#include <math.h>
#include <cstdint>

#define SEQ   4096
#define DM    768
#define NH    12
#define DH    64
#define QKVC  2304          // 3 * DM
#define SCALE 0.125f        // 1/sqrt(64)
#define NEG   -1.0e30f

// ------------------------- scratch (__device__ globals) --------------------
__device__ __half g_q16[NH * SEQ * DH];     // [h][s][d], pre-scaled by SCALE
__device__ __half g_k16[NH * SEQ * DH];     // [h][s][d]
__device__ __half g_v16[NH * SEQ * DH];     // [h][s][d]
__device__ __half g_attn16[SEQ * DM];       // attention out fp16, [s][h*64+d]

// ---------------------------- PTX helpers ----------------------------------
__device__ __forceinline__ uint32_t smem_u32(const void* p) {
    uint32_t a;
    asm("{ .reg .u64 t; cvta.to.shared.u64 t, %1; cvt.u32.u64 %0, t; }" : "=r"(a) : "l"(p));
    return a;
}
__device__ __forceinline__ void ldmx4(uint32_t* r, uint32_t addr) {
    asm volatile("ldmatrix.sync.aligned.m8n8.x4.shared.b16 {%0,%1,%2,%3}, [%4];"
        : "=r"(r[0]), "=r"(r[1]), "=r"(r[2]), "=r"(r[3]) : "r"(addr));
}
__device__ __forceinline__ void ldmx4t(uint32_t* r, uint32_t addr) {
    asm volatile("ldmatrix.sync.aligned.m8n8.x4.trans.shared.b16 {%0,%1,%2,%3}, [%4];"
        : "=r"(r[0]), "=r"(r[1]), "=r"(r[2]), "=r"(r[3]) : "r"(addr));
}
__device__ __forceinline__ void mma16816(float* d, const uint32_t* a,
                                         const uint32_t* b, const float* c) {
    asm volatile(
        "mma.sync.aligned.m16n8k16.row.col.f32.f16.f16.f32 "
        "{%0,%1,%2,%3}, {%4,%5,%6,%7}, {%8,%9}, {%10,%11,%12,%13};"
        : "=f"(d[0]), "=f"(d[1]), "=f"(d[2]), "=f"(d[3])
        : "r"(a[0]), "r"(a[1]), "r"(a[2]), "r"(a[3]),
          "r"(b[0]), "r"(b[1]),
          "f"(c[0]), "f"(c[1]), "f"(c[2]), "f"(c[3]));
}
__device__ __forceinline__ uint32_t packh2(float x, float y) {
    __half2 h = __floats2half2_rn(x, y);
    return *(uint32_t*)&h;
}

#define GSTR 72   // smem row stride in halves (conflict-free ldmatrix)

// ---------------------------------------------------------------------------
// HMMA GEMM: C[M,N] = A[M,K] @ B[N,K]^T + bias[N]
// 128x128 CTA tile, 8 warps (2x4), warp = 64x32, K-tile = 64.
// AMODE: 0 = A fp32 (convert inline), 1 = A fp16.
// EPI:   0 = scatter QKV to per-head fp16 buffers, 1 = fp32 C + bias.
// ---------------------------------------------------------------------------
template<int AMODE, int EPI>
__global__ __launch_bounds__(256) void gemm_mma(
    const void* __restrict__ Ap, const float* __restrict__ B,
    const float* __restrict__ bias, float* __restrict__ Cout,
    int M, int N, int K)
{
    __shared__ __half smA[128 * GSTR];
    __shared__ __half smB[128 * GSTR];

    const int tid  = threadIdx.x;
    const int lane = tid & 31;
    const int wid  = tid >> 5;
    const int m0   = blockIdx.y * 128;
    const int n0   = blockIdx.x * 128;
    const int wm   = (wid >> 2) * 64;   // warp row offset in tile
    const int wn   = (wid & 3) * 32;    // warp col offset in tile

    const uint32_t smAb = smem_u32(smA);
    const uint32_t smBb = smem_u32(smB);

    float Cf[4][4][4];
#pragma unroll
    for (int mt = 0; mt < 4; mt++)
#pragma unroll
        for (int nb = 0; nb < 4; nb++)
#pragma unroll
            for (int j = 0; j < 4; j++) Cf[mt][nb][j] = 0.f;

    for (int kt = 0; kt < K; kt += 64) {
        // ---- stage A (fp32->fp16 or fp16 copy) ----
        if (AMODE == 0) {
            const float* A = (const float*)Ap;
#pragma unroll
            for (int i = 0; i < 8; i++) {
                int idx = i * 256 + tid;
                int row = idx >> 4, c4 = (idx & 15) * 4;
                float4 v = *(const float4*)(A + (size_t)(m0 + row) * K + kt + c4);
                uint2 u; u.x = packh2(v.x, v.y); u.y = packh2(v.z, v.w);
                *(uint2*)(smA + row * GSTR + c4) = u;
            }
        } else {
            const __half* A = (const __half*)Ap;
#pragma unroll
            for (int i = 0; i < 4; i++) {
                int idx = i * 256 + tid;
                int row = idx >> 3, g = idx & 7;
                *(uint4*)(smA + row * GSTR + g * 8) =
                    *(const uint4*)(A + (size_t)(m0 + row) * K + kt + g * 8);
            }
        }
        // ---- stage B (fp32->fp16) ----
        {
#pragma unroll
            for (int i = 0; i < 8; i++) {
                int idx = i * 256 + tid;
                int row = idx >> 4, c4 = (idx & 15) * 4;
                float4 v = *(const float4*)(B + (size_t)(n0 + row) * K + kt + c4);
                uint2 u; u.x = packh2(v.x, v.y); u.y = packh2(v.z, v.w);
                *(uint2*)(smB + row * GSTR + c4) = u;
            }
        }
        __syncthreads();

        // ---- B fragments for the whole K-tile ----
        uint32_t bf[4][8];
#pragma unroll
        for (int nb = 0; nb < 4; nb++) {
            uint32_t rowa = wn + nb * 8 + (lane & 7);
            uint32_t cola = (lane >> 3) * 8;
            ldmx4(bf[nb],     smBb + (rowa * GSTR + cola) * 2);        // k 0..31
            ldmx4(bf[nb] + 4, smBb + (rowa * GSTR + 32 + cola) * 2);   // k 32..63
        }
        // ---- A fragments + MMAs per m-subtile ----
#pragma unroll
        for (int mt = 0; mt < 4; mt++) {
            uint32_t af[4][4];
            uint32_t rowa = wm + mt * 16 + (lane & 15);
            uint32_t cola = (lane >> 4) * 8;
#pragma unroll
            for (int kb = 0; kb < 4; kb++)
                ldmx4(af[kb], smAb + (rowa * GSTR + kb * 16 + cola) * 2);
#pragma unroll
            for (int nb = 0; nb < 4; nb++)
#pragma unroll
                for (int kb = 0; kb < 4; kb++)
                    mma16816(Cf[mt][nb], af[kb], &bf[nb][2 * kb], Cf[mt][nb]);
        }
        __syncthreads();
    }

    // ---- epilogue ----
#pragma unroll
    for (int mt = 0; mt < 4; mt++) {
#pragma unroll
        for (int nb = 0; nb < 4; nb++) {
            int r0  = m0 + wm + mt * 16 + (lane >> 2);
            int col = n0 + wn + nb * 8 + (lane & 3) * 2;
            float b0v = bias[col], b1v = bias[col + 1];
            if (EPI == 0) {
                int seg  = col / DM;               // 0=Q 1=K 2=V
                int cm   = col - seg * DM;
                int head = cm >> 6, dim = cm & 63;
                __half* dst = (seg == 0) ? g_q16 : (seg == 1) ? g_k16 : g_v16;
                float sc = (seg == 0) ? SCALE : 1.f;
                __half2 w0 = __floats2half2_rn((Cf[mt][nb][0] + b0v) * sc,
                                               (Cf[mt][nb][1] + b1v) * sc);
                __half2 w1 = __floats2half2_rn((Cf[mt][nb][2] + b0v) * sc,
                                               (Cf[mt][nb][3] + b1v) * sc);
                *(__half2*)(dst + ((size_t)head * SEQ + r0) * DH + dim)     = w0;
                *(__half2*)(dst + ((size_t)head * SEQ + r0 + 8) * DH + dim) = w1;
            } else {
                float2 w0 = make_float2(Cf[mt][nb][0] + b0v, Cf[mt][nb][1] + b1v);
                float2 w1 = make_float2(Cf[mt][nb][2] + b0v, Cf[mt][nb][3] + b1v);
                *(float2*)(Cout + (size_t)r0 * N + col)       = w0;
                *(float2*)(Cout + (size_t)(r0 + 8) * N + col) = w1;
            }
        }
    }
}

// ---------------------------------------------------------------------------
// HMMA flash attention.  grid (NH, SEQ/128), 256 threads (8 warps).
// Warp w owns q rows qt*128 + w*16 .. +15.  64-key tiles.
// ---------------------------------------------------------------------------
#define KSTR 72

__global__ __launch_bounds__(256) void attn_mma_kernel()
{
    __shared__ __half sm[128 * KSTR];    // Q staging (128x64) -> later K(64)+V(64)

    const int tid  = threadIdx.x;
    const int wid  = tid >> 5;
    const int lane = tid & 31;
    const int h    = blockIdx.x;
    const int qt   = (int)gridDim.y - 1 - (int)blockIdx.y;   // long blocks first
    const int q0   = qt * 128;
    const int wq   = q0 + wid * 16;      // warp's first q row

    const uint32_t smb = smem_u32(sm);

    // ---- stage Q tile, extract A-fragments ----
    {
        const __half* qg = g_q16 + ((size_t)h * SEQ + q0) * DH;
#pragma unroll
        for (int i = 0; i < 4; i++) {
            int idx = i * 256 + tid;
            int row = idx >> 3;
            int g   = idx & 7;
            *(uint4*)(sm + row * KSTR + g * 8) = *((const uint4*)(qg + (size_t)row * DH) + g);
        }
    }
    __syncthreads();

    uint32_t qa[4][4];
    {
        int row  = wid * 16 + (lane & 15);
        int colh = (lane >> 4) * 8;
#pragma unroll
        for (int kb = 0; kb < 4; kb++)
            ldmx4(qa[kb], smb + (uint32_t)(row * KSTR + kb * 16 + colh) * 2);
    }
    __syncthreads();

    __half* smK = sm;
    __half* smV = sm + 64 * KSTR;
    const uint32_t smKb = smb;
    const uint32_t smVb = smb + 64 * KSTR * 2;

    float O[8][4];
#pragma unroll
    for (int d = 0; d < 8; d++)
#pragma unroll
        for (int j = 0; j < 4; j++) O[d][j] = 0.f;
    float m0 = NEG, m1 = NEG, l0 = 0.f, l1 = 0.f;

    const int ktiles = (qt + 1) * 2;
    for (int t = 0; t < ktiles; t++) {
        const int k0 = t * 64;

        {
            const __half* kg = g_k16 + ((size_t)h * SEQ + k0) * DH;
            const __half* vg = g_v16 + ((size_t)h * SEQ + k0) * DH;
#pragma unroll
            for (int i = 0; i < 2; i++) {
                int idx = i * 256 + tid;
                int row = idx >> 3;
                int g   = idx & 7;
                *(uint4*)(smK + row * KSTR + g * 8) = *((const uint4*)(kg + (size_t)row * DH) + g);
                *(uint4*)(smV + row * KSTR + g * 8) = *((const uint4*)(vg + (size_t)row * DH) + g);
            }
        }
        __syncthreads();

        if (k0 <= wq + 15) {
            // ---- S = Q @ K^T ----
            float c[8][4];
#pragma unroll
            for (int nb = 0; nb < 8; nb++)
#pragma unroll
                for (int j = 0; j < 4; j++) c[nb][j] = 0.f;

#pragma unroll
            for (int nb = 0; nb < 8; nb++) {
                uint32_t kk[8];
                uint32_t rowa = nb * 8 + (lane & 7);
                uint32_t cola = (lane >> 3) * 8;
                ldmx4(kk,     smKb + (rowa * KSTR + cola) * 2);
                ldmx4(kk + 4, smKb + (rowa * KSTR + 32 + cola) * 2);
#pragma unroll
                for (int kb = 0; kb < 4; kb++)
                    mma16816(c[nb], qa[kb], kk + kb * 2, c[nb]);
            }

            // ---- causal mask ----
            if (k0 + 63 > wq) {
                int r0 = wq + (lane >> 2);
                int r1 = r0 + 8;
                int cb = k0 + (lane & 3) * 2;
#pragma unroll
                for (int nb = 0; nb < 8; nb++) {
                    int col = cb + nb * 8;
                    if (col     > r0) c[nb][0] = NEG;
                    if (col + 1 > r0) c[nb][1] = NEG;
                    if (col     > r1) c[nb][2] = NEG;
                    if (col + 1 > r1) c[nb][3] = NEG;
                }
            }

            // ---- online softmax ----
            float tm0 = NEG, tm1 = NEG;
#pragma unroll
            for (int nb = 0; nb < 8; nb++) {
                tm0 = fmaxf(tm0, fmaxf(c[nb][0], c[nb][1]));
                tm1 = fmaxf(tm1, fmaxf(c[nb][2], c[nb][3]));
            }
            tm0 = fmaxf(tm0, __shfl_xor_sync(0xffffffffu, tm0, 1));
            tm0 = fmaxf(tm0, __shfl_xor_sync(0xffffffffu, tm0, 2));
            tm1 = fmaxf(tm1, __shfl_xor_sync(0xffffffffu, tm1, 1));
            tm1 = fmaxf(tm1, __shfl_xor_sync(0xffffffffu, tm1, 2));

            float mn0 = fmaxf(m0, tm0), mn1 = fmaxf(m1, tm1);
            float a0  = __expf(m0 - mn0), a1 = __expf(m1 - mn1);
            float ps0 = 0.f, ps1 = 0.f;
#pragma unroll
            for (int nb = 0; nb < 8; nb++) {
                c[nb][0] = __expf(c[nb][0] - mn0);
                c[nb][1] = __expf(c[nb][1] - mn0);
                c[nb][2] = __expf(c[nb][2] - mn1);
                c[nb][3] = __expf(c[nb][3] - mn1);
                ps0 += c[nb][0] + c[nb][1];
                ps1 += c[nb][2] + c[nb][3];
            }
            ps0 += __shfl_xor_sync(0xffffffffu, ps0, 1);
            ps0 += __shfl_xor_sync(0xffffffffu, ps0, 2);
            ps1 += __shfl_xor_sync(0xffffffffu, ps1, 1);
            ps1 += __shfl_xor_sync(0xffffffffu, ps1, 2);
            l0 = l0 * a0 + ps0;  m0 = mn0;
            l1 = l1 * a1 + ps1;  m1 = mn1;

#pragma unroll
            for (int d = 0; d < 8; d++) {
                O[d][0] *= a0; O[d][1] *= a0;
                O[d][2] *= a1; O[d][3] *= a1;
            }

            // ---- repack P ----
            uint32_t pa[4][4];
#pragma unroll
            for (int kb = 0; kb < 4; kb++) {
                pa[kb][0] = packh2(c[2 * kb][0],     c[2 * kb][1]);
                pa[kb][1] = packh2(c[2 * kb][2],     c[2 * kb][3]);
                pa[kb][2] = packh2(c[2 * kb + 1][0], c[2 * kb + 1][1]);
                pa[kb][3] = packh2(c[2 * kb + 1][2], c[2 * kb + 1][3]);
            }

            // ---- O += P @ V ----
#pragma unroll
            for (int db = 0; db < 8; db++) {
                uint32_t v0[4], v1[4];
                ldmx4t(v0, smVb + (uint32_t)((lane)      * KSTR + db * 8) * 2);
                ldmx4t(v1, smVb + (uint32_t)((32 + lane) * KSTR + db * 8) * 2);
                mma16816(O[db], pa[0], v0,     O[db]);
                mma16816(O[db], pa[1], v0 + 2, O[db]);
                mma16816(O[db], pa[2], v1,     O[db]);
                mma16816(O[db], pa[3], v1 + 2, O[db]);
            }
        }
        __syncthreads();
    }

    // ---- epilogue: divide by l, store fp16 for out-proj ----
    const float inv0 = 1.f / l0, inv1 = 1.f / l1;
    const int r0 = wq + (lane >> 2);
    const int r1 = r0 + 8;
    __half* o0 = g_attn16 + (size_t)r0 * DM + h * DH + (lane & 3) * 2;
    __half* o1 = g_attn16 + (size_t)r1 * DM + h * DH + (lane & 3) * 2;
#pragma unroll
    for (int db = 0; db < 8; db++) {
        *(__half2*)(o0 + db * 8) = __floats2half2_rn(O[db][0] * inv0, O[db][1] * inv0);
        *(__half2*)(o1 + db * 8) = __floats2half2_rn(O[db][2] * inv1, O[db][3] * inv1);
    }
}

// ---------------------------------------------------------------------------
extern "C" void kernel_launch(void* const* d_in, const int* in_sizes, int n_in,
                              void* d_out, int out_size)
{
    const float* x     = (const float*)d_in[0];
    const float* W_in  = (const float*)d_in[1];
    const float* b_in  = (const float*)d_in[2];
    const float* W_out = (const float*)d_in[3];
    const float* b_out = (const float*)d_in[4];
    float* out = (float*)d_out;

    __half* attn16_p;
    cudaGetSymbolAddress((void**)&attn16_p, g_attn16);

    // 1) QKV projection (HMMA), scatter fp16 Q(scaled)/K/V per-head
    {
        dim3 grid(QKVC / 128, SEQ / 128);
        gemm_mma<0, 0><<<grid, 256>>>(x, W_in, b_in, nullptr, SEQ, QKVC, DM);
    }
    // 2) HMMA causal flash attention -> g_attn16
    {
        dim3 grid(NH, SEQ / 128);
        attn_mma_kernel<<<grid, 256>>>();
    }
    // 3) out = attn @ W_out^T + b_out (HMMA, fp16 A direct)
    {
        dim3 grid(DM / 128, SEQ / 128);
        gemm_mma<1, 1><<<grid, 256>>>(attn16_p, W_out, b_out, out, SEQ, DM, DM);
    }
}